// round 8
// baseline (speedup 1.0000x reference)
#include <cuda_runtime.h>
#include <cuda_bf16.h>
#include <math.h>
#include <stdint.h>

#define CB  128
#define CIN 256
#define NSP 4096
#define NB  4

typedef unsigned long long u64;

// ===================== helpers =====================
__device__ __forceinline__ uint32_t smem_to_u32(const void* p) {
    uint32_t a;
    asm("{ .reg .u64 t; cvta.to.shared.u64 t, %1; cvt.u32.u64 %0, t; }" : "=r"(a) : "l"(p));
    return a;
}
__device__ __forceinline__ void ldsm4(uint32_t* r, uint32_t a) {
    asm volatile("ldmatrix.sync.aligned.m8n8.x4.shared.b16 {%0,%1,%2,%3}, [%4];"
        : "=r"(r[0]), "=r"(r[1]), "=r"(r[2]), "=r"(r[3]) : "r"(a));
}
__device__ __forceinline__ void mma16816(float* c, const uint32_t* a, uint32_t b0, uint32_t b1) {
    asm volatile("mma.sync.aligned.m16n8k16.row.col.f32.bf16.bf16.f32 "
        "{%0,%1,%2,%3}, {%4,%5,%6,%7}, {%8,%9}, {%0,%1,%2,%3};"
        : "+f"(c[0]), "+f"(c[1]), "+f"(c[2]), "+f"(c[3])
        : "r"(a[0]), "r"(a[1]), "r"(a[2]), "r"(a[3]), "r"(b0), "r"(b1));
}
// FFMA2 helpers (SIMT kernels)
__device__ __forceinline__ u64 pk2(float a, float b) {
    u64 r; asm("mov.b64 %0, {%1, %2};" : "=l"(r) : "f"(a), "f"(b)); return r;
}
__device__ __forceinline__ void upk2(u64 v, float& a, float& b) {
    asm("mov.b64 {%0, %1}, %2;" : "=f"(a), "=f"(b) : "l"(v));
}
__device__ __forceinline__ u64 fma2(u64 a, u64 b, u64 c) {
    u64 d; asm("fma.rn.f32x2 %0, %1, %2, %3;" : "=l"(d) : "l"(a), "l"(b), "l"(c)); return d;
}

// ===================== scratch =====================
__device__ float g_T[(size_t)NB * CB * NSP];
__device__ float g_P[(size_t)NB * CB * NSP];
__device__ float g_G[(size_t)NB * CB * NSP];
__device__ float g_Y[(size_t)NB * CB * NSP];
__device__ float g_S[(size_t)NB * NSP * NSP];          // expS fp32
__device__ float g_Zp[NB * 32 * NSP];
__device__ float g_Zr[NB * NSP];
__device__ __nv_bfloat16 g_Thi[(size_t)NB * NSP * CB]; // (n,k)
__device__ __nv_bfloat16 g_Tlo[(size_t)NB * NSP * CB];
__device__ __nv_bfloat16 g_Phi[(size_t)NB * NSP * CB]; // Pt (n,k)
__device__ __nv_bfloat16 g_Plo[(size_t)NB * NSP * CB];
__device__ __nv_bfloat16 g_Ghi[(size_t)NB * CB * NSP]; // Gt' (c,m), scaled by 1/Z
__device__ __nv_bfloat16 g_Glo[(size_t)NB * CB * NSP];

// SMEM layouts (row stride 272B = 136 bf16: conflict-free ldmatrix)
#define SC_AHI 0
#define SC_ALO 34816
#define SC_BHI 69632
#define SC_BLO 104448
#define SC_BYTES 139264

#define Y_AHI 0
#define Y_ALO 17408
#define Y_BHI 34816
#define Y_BLO 69632
#define Y_BYTES 104448

// ---------------------------------------------------------------------------
// Kernel 1: T/P/G 1x1 convs (SIMT FFMA2). grid (32,1,12)
// ---------------------------------------------------------------------------
__global__ __launch_bounds__(256, 2) void conv_tpg_kernel(
    const float* __restrict__ x,
    const float* __restrict__ tw, const float* __restrict__ tbias,
    const float* __restrict__ pw, const float* __restrict__ pbias,
    const float* __restrict__ gw, const float* __restrict__ gbias)
{
    int z = blockIdx.z;
    int b = z / 3, mat = z - b * 3;
    const float* W    = (mat == 0) ? tw    : (mat == 1) ? pw    : gw;
    const float* bias = (mat == 0) ? tbias : (mat == 1) ? pbias : gbias;
    float* Cout = ((mat == 0) ? g_T : (mat == 1) ? g_P : g_G) + (size_t)b * CB * NSP;
    const float* Bx = x + (size_t)b * CIN * NSP;

    __shared__ __align__(16) float As[8][132];
    __shared__ __align__(16) float Bs[8][128];
    int tid  = threadIdx.x;
    int aRow = tid >> 1, aCol = (tid & 1) << 2;
    int bRow = tid >> 5, bCol = (tid & 31) << 2;
    int ty = tid >> 4, tx = tid & 15;
    int colBase = blockIdx.x << 7;

    u64 acc[8][4];
#pragma unroll
    for (int i = 0; i < 8; i++)
#pragma unroll
        for (int jp = 0; jp < 4; jp++) acc[i][jp] = pk2(0.f, 0.f);

    for (int k0 = 0; k0 < CIN; k0 += 8) {
        float4 av = *(const float4*)(W + (size_t)aRow * CIN + k0 + aCol);
        As[aCol + 0][aRow] = av.x;
        As[aCol + 1][aRow] = av.y;
        As[aCol + 2][aRow] = av.z;
        As[aCol + 3][aRow] = av.w;
        *(float4*)&Bs[bRow][bCol] =
            *(const float4*)(Bx + (size_t)(k0 + bRow) * NSP + colBase + bCol);
        __syncthreads();
#pragma unroll
        for (int k = 0; k < 8; k++) {
            float ra[8];
            *(float4*)(ra)     = *(const float4*)&As[k][ty << 2];
            *(float4*)(ra + 4) = *(const float4*)&As[k][64 + (ty << 2)];
            const u64* bp0 = (const u64*)&Bs[k][tx << 2];
            const u64* bp1 = (const u64*)&Bs[k][64 + (tx << 2)];
            u64 rb[4] = {bp0[0], bp0[1], bp1[0], bp1[1]};
#pragma unroll
            for (int i = 0; i < 8; i++) {
                u64 aa = pk2(ra[i], ra[i]);
#pragma unroll
                for (int jp = 0; jp < 4; jp++)
                    acc[i][jp] = fma2(aa, rb[jp], acc[i][jp]);
            }
        }
        __syncthreads();
    }
#pragma unroll
    for (int i = 0; i < 8; i++) {
        int row = ((i >> 2) << 6) + (ty << 2) + (i & 3);
        float bv = bias[row];
#pragma unroll
        for (int jh = 0; jh < 2; jh++) {
            float4 v;
            upk2(acc[i][2 * jh],     v.x, v.y);
            upk2(acc[i][2 * jh + 1], v.z, v.w);
            v.x += bv; v.y += bv; v.z += bv; v.w += bv;
            *(float4*)(Cout + (size_t)row * NSP + colBase + (jh << 6) + (tx << 2)) = v;
        }
    }
}

// ---------------------------------------------------------------------------
// Kernel 2a: T -> bf16 hi/lo. grid 2048, 256 thr
// ---------------------------------------------------------------------------
__global__ __launch_bounds__(256) void cvtT_kernel()
{
    size_t i = ((size_t)blockIdx.x * 256 + threadIdx.x) * 4;
    float4 v = *(const float4*)(g_T + i);
    __nv_bfloat16 hx = __float2bfloat16_rn(v.x), hy = __float2bfloat16_rn(v.y);
    __nv_bfloat16 hz = __float2bfloat16_rn(v.z), hw = __float2bfloat16_rn(v.w);
    __nv_bfloat162 h01(hx, hy), h23(hz, hw);
    __nv_bfloat162 l01(__float2bfloat16_rn(v.x - __bfloat162float(hx)),
                       __float2bfloat16_rn(v.y - __bfloat162float(hy)));
    __nv_bfloat162 l23(__float2bfloat16_rn(v.z - __bfloat162float(hz)),
                       __float2bfloat16_rn(v.w - __bfloat162float(hw)));
    *(uint2*)(g_Thi + i) = make_uint2(*(uint32_t*)&h01, *(uint32_t*)&h23);
    *(uint2*)(g_Tlo + i) = make_uint2(*(uint32_t*)&l01, *(uint32_t*)&l23);
}

// ---------------------------------------------------------------------------
// Kernel 2b: P (128,4096) -> Pt (4096,128) bf16 hi/lo. grid (128,4,NB), blk (32,8)
// ---------------------------------------------------------------------------
__global__ __launch_bounds__(256) void trP_kernel()
{
    int b = blockIdx.z;
    const float* P = g_P + (size_t)b * CB * NSP;
    __shared__ float sm[32][33];
    int tx = threadIdx.x, ty = threadIdx.y;
    int n0 = blockIdx.x << 5, k0 = blockIdx.y << 5;
#pragma unroll
    for (int i = 0; i < 4; i++)
        sm[ty + i * 8][tx] = P[(size_t)(k0 + ty + i * 8) * NSP + n0 + tx];
    __syncthreads();
#pragma unroll
    for (int i = 0; i < 4; i++) {
        int n = n0 + ty + i * 8, k = k0 + tx;
        float v = sm[tx][ty + i * 8];
        __nv_bfloat16 h = __float2bfloat16_rn(v);
        g_Phi[((size_t)b * NSP + n) * CB + k] = h;
        g_Plo[((size_t)b * NSP + n) * CB + k] = __float2bfloat16_rn(v - __bfloat162float(h));
    }
}

// ---------------------------------------------------------------------------
// Kernel 3: expS(128x128 tile) = exp( T @ Pt^T ) via mma.sync bf16 3-pass
// grid (32 coltile, 32 rowtile, NB), 256 thr (8 warps, 32x64 warp tiles)
// Pass-ordered MMA issue: within each pass all 16 mma target distinct accs.
// ---------------------------------------------------------------------------
__global__ __launch_bounds__(256, 1) void scores_mma_kernel()
{
    extern __shared__ __align__(16) char smem[];
    const int tid = threadIdx.x;
    const int wid = tid >> 5, lane = tid & 31;
    const int b = blockIdx.z;
    const int rowBase = blockIdx.y << 7;
    const int colBase = blockIdx.x << 7;

    {   // stage A (T rows) and B (Pt rows) hi/lo, row stride 272B
        const __nv_bfloat16* Ah = g_Thi + ((size_t)b * NSP + rowBase) * CB;
        const __nv_bfloat16* Al = g_Tlo + ((size_t)b * NSP + rowBase) * CB;
        const __nv_bfloat16* Bh = g_Phi + ((size_t)b * NSP + colBase) * CB;
        const __nv_bfloat16* Bl = g_Plo + ((size_t)b * NSP + colBase) * CB;
        int r = tid >> 1, half = tid & 1;
#pragma unroll
        for (int j = 0; j < 8; j++) {
            int k = half * 64 + j * 8;
            size_t gi = (size_t)r * CB + k;
            uint32_t so = r * 272 + k * 2;
            *(uint4*)(smem + SC_AHI + so) = *(const uint4*)(Ah + gi);
            *(uint4*)(smem + SC_ALO + so) = *(const uint4*)(Al + gi);
            *(uint4*)(smem + SC_BHI + so) = *(const uint4*)(Bh + gi);
            *(uint4*)(smem + SC_BLO + so) = *(const uint4*)(Bl + gi);
        }
    }
    __syncthreads();

    const uint32_t sb = smem_to_u32(smem);
    const int mrow = (wid >> 1) * 32, ncol = (wid & 1) * 64;
    const int aR = lane & 15, aK = (lane >> 4) * 8;
    const int bN = (lane & 7) + ((lane >> 4) << 3), bK = ((lane >> 3) & 1) * 8;

    float acc[2][8][4];
#pragma unroll
    for (int mi = 0; mi < 2; mi++)
#pragma unroll
        for (int n = 0; n < 8; n++)
#pragma unroll
            for (int q = 0; q < 4; q++) acc[mi][n][q] = 0.f;

#pragma unroll
    for (int ks = 0; ks < 8; ks++) {
        int k0 = ks * 16;
        uint32_t ahi[2][4], alo[2][4], bhi[4][4], blo[4][4];
#pragma unroll
        for (int mi = 0; mi < 2; mi++) {
            uint32_t ad = sb + SC_AHI + (mrow + mi * 16 + aR) * 272 + (k0 + aK) * 2;
            ldsm4(ahi[mi], ad);
            ldsm4(alo[mi], ad + (SC_ALO - SC_AHI));
        }
#pragma unroll
        for (int nj = 0; nj < 4; nj++) {
            uint32_t bd = sb + SC_BHI + (ncol + nj * 16 + bN) * 272 + (k0 + bK) * 2;
            ldsm4(bhi[nj], bd);
            ldsm4(blo[nj], bd + (SC_BLO - SC_BHI));
        }
        // pass 1: hi*hi — 16 independent accumulators
#pragma unroll
        for (int nj = 0; nj < 4; nj++)
#pragma unroll
            for (int mi = 0; mi < 2; mi++) {
                mma16816(acc[mi][nj * 2],     ahi[mi], bhi[nj][0], bhi[nj][1]);
                mma16816(acc[mi][nj * 2 + 1], ahi[mi], bhi[nj][2], bhi[nj][3]);
            }
        // pass 2: hi*lo
#pragma unroll
        for (int nj = 0; nj < 4; nj++)
#pragma unroll
            for (int mi = 0; mi < 2; mi++) {
                mma16816(acc[mi][nj * 2],     ahi[mi], blo[nj][0], blo[nj][1]);
                mma16816(acc[mi][nj * 2 + 1], ahi[mi], blo[nj][2], blo[nj][3]);
            }
        // pass 3: lo*hi
#pragma unroll
        for (int nj = 0; nj < 4; nj++)
#pragma unroll
            for (int mi = 0; mi < 2; mi++) {
                mma16816(acc[mi][nj * 2],     alo[mi], bhi[nj][0], bhi[nj][1]);
                mma16816(acc[mi][nj * 2 + 1], alo[mi], bhi[nj][2], bhi[nj][3]);
            }
    }
    __syncthreads();   // tiles no longer needed; reuse smem for column reduction

    float (*sRed)[129] = (float(*)[129])smem;
    float* Sout = g_S + (size_t)b * NSP * NSP;
    const int g = lane >> 2, tig = lane & 3;
#pragma unroll
    for (int mi = 0; mi < 2; mi++)
#pragma unroll
        for (int rr = 0; rr < 2; rr++) {
            int rowl = mrow + mi * 16 + g + rr * 8;
            float* orow = Sout + (size_t)(rowBase + rowl) * NSP + colBase;
#pragma unroll
            for (int ni = 0; ni < 8; ni++) {
                int coll = ncol + ni * 8 + tig * 2;
                float e0 = __expf(acc[mi][ni][rr * 2 + 0]);
                float e1 = __expf(acc[mi][ni][rr * 2 + 1]);
                *(float2*)(orow + coll) = make_float2(e0, e1);
                sRed[rowl][coll]     = e0;
                sRed[rowl][coll + 1] = e1;
            }
        }
    __syncthreads();
    if (tid < 128) {
        float s = 0.f;
#pragma unroll 16
        for (int r = 0; r < 128; r++) s += sRed[r][tid];
        g_Zp[(b * 32 + blockIdx.y) * NSP + colBase + tid] = s;
    }
}

// ---------------------------------------------------------------------------
// Kernel 4: 1/Z per column. grid 64, 256 thr
// ---------------------------------------------------------------------------
__global__ __launch_bounds__(256) void zreduce_kernel()
{
    int t = blockIdx.x * 256 + threadIdx.x;
    int b = t >> 12, m = t & (NSP - 1);
    float s = 0.f;
#pragma unroll 8
    for (int r = 0; r < 32; r++) s += g_Zp[(b * 32 + r) * NSP + m];
    g_Zr[t] = 1.0f / s;
}

// ---------------------------------------------------------------------------
// Kernel 5: Gt'(c,m) = Gview[m][c] * Zr[m], bf16 hi/lo. grid (128,4,NB), blk (32,8)
// ---------------------------------------------------------------------------
__global__ __launch_bounds__(256) void gscale_kernel()
{
    int b = blockIdx.z;
    const float* Gf = g_G + (size_t)b * CB * NSP;   // flat view (m, c) ld=CB
    const float* Zr = g_Zr + b * NSP;
    __shared__ float sm[32][33];
    int tx = threadIdx.x, ty = threadIdx.y;
    int m0 = blockIdx.x << 5, c0 = blockIdx.y << 5;
#pragma unroll
    for (int i = 0; i < 4; i++) {
        int m = m0 + ty + i * 8;
        sm[ty + i * 8][tx] = Gf[(size_t)m * CB + c0 + tx] * Zr[m];
    }
    __syncthreads();
#pragma unroll
    for (int i = 0; i < 4; i++) {
        int c = c0 + ty + i * 8, m = m0 + tx;
        float v = sm[tx][ty + i * 8];
        __nv_bfloat16 h = __float2bfloat16_rn(v);
        g_Ghi[((size_t)b * CB + c) * NSP + m] = h;
        g_Glo[((size_t)b * CB + c) * NSP + m] = __float2bfloat16_rn(v - __bfloat162float(h));
    }
}

// ---------------------------------------------------------------------------
// Kernel 6: Y(64x128 tile) = expS @ (Gt')^T via mma.sync, K=4096 in 32 chunks
// grid (64 rowtile, NB), 256 thr (8 warps, 16x64 warp tiles)
// ---------------------------------------------------------------------------
__global__ __launch_bounds__(256, 1) void y_mma_kernel()
{
    extern __shared__ __align__(16) char smem[];
    const int tid = threadIdx.x;
    const int wid = tid >> 5, lane = tid & 31;
    const int b = blockIdx.y;
    const int rowBase = blockIdx.x << 6;

    const uint32_t sb = smem_to_u32(smem);
    const int mrow = (wid >> 1) * 16, ncol = (wid & 1) * 64;
    const int aR = lane & 15, aK = (lane >> 4) * 8;
    const int bN = (lane & 7) + ((lane >> 4) << 3), bK = ((lane >> 3) & 1) * 8;

    float acc[8][4];
#pragma unroll
    for (int n = 0; n < 8; n++)
#pragma unroll
        for (int q = 0; q < 4; q++) acc[n][q] = 0.f;

    const int ar = tid >> 2, aseg = tid & 3;
    const int bc = tid >> 1, bhalf = tid & 1;
    const float* Arow = g_S + (size_t)b * NSP * NSP + (size_t)(rowBase + ar) * NSP;
    const __nv_bfloat16* Bh0 = g_Ghi + ((size_t)b * CB + bc) * NSP;
    const __nv_bfloat16* Bl0 = g_Glo + ((size_t)b * CB + bc) * NSP;

    for (int kt = 0; kt < 32; kt++) {
        int kg = kt << 7;
        // A: expS fp32 -> hi/lo bf16 into SMEM
#pragma unroll
        for (int j = 0; j < 8; j++) {
            int k = aseg * 32 + j * 4;
            float4 v = *(const float4*)(Arow + kg + k);
            __nv_bfloat16 hx = __float2bfloat16_rn(v.x), hy = __float2bfloat16_rn(v.y);
            __nv_bfloat16 hz = __float2bfloat16_rn(v.z), hw = __float2bfloat16_rn(v.w);
            __nv_bfloat162 h01(hx, hy), h23(hz, hw);
            __nv_bfloat162 l01(__float2bfloat16_rn(v.x - __bfloat162float(hx)),
                               __float2bfloat16_rn(v.y - __bfloat162float(hy)));
            __nv_bfloat162 l23(__float2bfloat16_rn(v.z - __bfloat162float(hz)),
                               __float2bfloat16_rn(v.w - __bfloat162float(hw)));
            uint32_t so = ar * 272 + k * 2;
            *(uint2*)(smem + Y_AHI + so) = make_uint2(*(uint32_t*)&h01, *(uint32_t*)&h23);
            *(uint2*)(smem + Y_ALO + so) = make_uint2(*(uint32_t*)&l01, *(uint32_t*)&l23);
        }
        // B: Gt' hi/lo copy
#pragma unroll
        for (int j = 0; j < 8; j++) {
            int k = bhalf * 64 + j * 8;
            uint32_t so = bc * 272 + k * 2;
            *(uint4*)(smem + Y_BHI + so) = *(const uint4*)(Bh0 + kg + k);
            *(uint4*)(smem + Y_BLO + so) = *(const uint4*)(Bl0 + kg + k);
        }
        __syncthreads();
#pragma unroll
        for (int ks = 0; ks < 8; ks++) {
            int k0 = ks * 16;
            uint32_t ahi[4], alo[4], bhi[4][4], blo[4][4];
            uint32_t ad = sb + Y_AHI + (mrow + aR) * 272 + (k0 + aK) * 2;
            ldsm4(ahi, ad);
            ldsm4(alo, ad + (Y_ALO - Y_AHI));
#pragma unroll
            for (int nj = 0; nj < 4; nj++) {
                uint32_t bd = sb + Y_BHI + (ncol + nj * 16 + bN) * 272 + (k0 + bK) * 2;
                ldsm4(bhi[nj], bd);
                ldsm4(blo[nj], bd + (Y_BLO - Y_BHI));
            }
            // pass 1: hi*hi — 8 independent accs
#pragma unroll
            for (int nj = 0; nj < 4; nj++) {
                mma16816(acc[nj * 2],     ahi, bhi[nj][0], bhi[nj][1]);
                mma16816(acc[nj * 2 + 1], ahi, bhi[nj][2], bhi[nj][3]);
            }
            // pass 2: hi*lo
#pragma unroll
            for (int nj = 0; nj < 4; nj++) {
                mma16816(acc[nj * 2],     ahi, blo[nj][0], blo[nj][1]);
                mma16816(acc[nj * 2 + 1], ahi, blo[nj][2], blo[nj][3]);
            }
            // pass 3: lo*hi
#pragma unroll
            for (int nj = 0; nj < 4; nj++) {
                mma16816(acc[nj * 2],     alo, bhi[nj][0], bhi[nj][1]);
                mma16816(acc[nj * 2 + 1], alo, bhi[nj][2], bhi[nj][3]);
            }
        }
        __syncthreads();
    }

    const int g = lane >> 2, tig = lane & 3;
#pragma unroll
    for (int rr = 0; rr < 2; rr++) {
        int row = rowBase + mrow + g + rr * 8;
        float* yrow = g_Y + ((size_t)b * NSP + row) * CB;
#pragma unroll
        for (int ni = 0; ni < 8; ni++) {
            int col = ncol + ni * 8 + tig * 2;
            *(float2*)(yrow + col) = make_float2(acc[ni][rr * 2], acc[ni][rr * 2 + 1]);
        }
    }
}

// ---------------------------------------------------------------------------
// Kernel 7: Out = W_w @ Yview + W_b + x (SIMT FFMA2). grid (32,2,NB)
// ---------------------------------------------------------------------------
__global__ __launch_bounds__(256, 2) void out_kernel(
    const float* __restrict__ x,
    const float* __restrict__ Ww, const float* __restrict__ Wb,
    float* __restrict__ out)
{
    int b = blockIdx.z;
    const float* Byc = g_Y + (size_t)b * CB * NSP;   // (128,4096) flat view, ld=4096
    const float* xb  = x + (size_t)b * CIN * NSP;
    float* Cb_ = out + (size_t)b * CIN * NSP;

    __shared__ __align__(16) float As[8][132];
    __shared__ __align__(16) float Bs[8][128];
    int tid  = threadIdx.x;
    int aRow = tid >> 1, aCol = (tid & 1) << 2;
    int bRow = tid >> 5, bCol = (tid & 31) << 2;
    int ty = tid >> 4, tx = tid & 15;
    int rowBase = blockIdx.y << 7;
    int colBase = blockIdx.x << 7;

    u64 acc[8][4];
#pragma unroll
    for (int i = 0; i < 8; i++)
#pragma unroll
        for (int jp = 0; jp < 4; jp++) acc[i][jp] = pk2(0.f, 0.f);

    for (int k0 = 0; k0 < CB; k0 += 8) {
        float4 av = *(const float4*)(Ww + (size_t)(rowBase + aRow) * CB + k0 + aCol);
        As[aCol + 0][aRow] = av.x;
        As[aCol + 1][aRow] = av.y;
        As[aCol + 2][aRow] = av.z;
        As[aCol + 3][aRow] = av.w;
        *(float4*)&Bs[bRow][bCol] =
            *(const float4*)(Byc + (size_t)(k0 + bRow) * NSP + colBase + bCol);
        __syncthreads();
#pragma unroll
        for (int k = 0; k < 8; k++) {
            float ra[8];
            *(float4*)(ra)     = *(const float4*)&As[k][ty << 2];
            *(float4*)(ra + 4) = *(const float4*)&As[k][64 + (ty << 2)];
            const u64* bp0 = (const u64*)&Bs[k][tx << 2];
            const u64* bp1 = (const u64*)&Bs[k][64 + (tx << 2)];
            u64 rb[4] = {bp0[0], bp0[1], bp1[0], bp1[1]};
#pragma unroll
            for (int i = 0; i < 8; i++) {
                u64 aa = pk2(ra[i], ra[i]);
#pragma unroll
                for (int jp = 0; jp < 4; jp++)
                    acc[i][jp] = fma2(aa, rb[jp], acc[i][jp]);
            }
        }
        __syncthreads();
    }
#pragma unroll
    for (int i = 0; i < 8; i++) {
        int row = rowBase + ((i >> 2) << 6) + (ty << 2) + (i & 3);
        float bv = Wb[row];
#pragma unroll
        for (int jh = 0; jh < 2; jh++) {
            int col = colBase + (jh << 6) + (tx << 2);
            float4 xv = *(const float4*)(xb + (size_t)row * NSP + col);
            float4 v;
            upk2(acc[i][2 * jh],     v.x, v.y);
            upk2(acc[i][2 * jh + 1], v.z, v.w);
            v.x += bv + xv.x; v.y += bv + xv.y;
            v.z += bv + xv.z; v.w += bv + xv.w;
            *(float4*)(Cb_ + (size_t)row * NSP + col) = v;
        }
    }
}

// ---------------------------------------------------------------------------
extern "C" void kernel_launch(void* const* d_in, const int* in_sizes, int n_in,
                              void* d_out, int out_size)
{
    const float* x  = (const float*)d_in[0];
    const float* tw = (const float*)d_in[1];
    const float* tb = (const float*)d_in[2];
    const float* pw = (const float*)d_in[3];
    const float* pb = (const float*)d_in[4];
    const float* gw = (const float*)d_in[5];
    const float* gb = (const float*)d_in[6];
    const float* Ww = (const float*)d_in[7];
    const float* Wb = (const float*)d_in[8];
    float* out = (float*)d_out;

    cudaFuncSetAttribute(scores_mma_kernel, cudaFuncAttributeMaxDynamicSharedMemorySize, SC_BYTES);
    cudaFuncSetAttribute(y_mma_kernel, cudaFuncAttributeMaxDynamicSharedMemorySize, Y_BYTES);

    conv_tpg_kernel<<<dim3(32, 1, 12), 256>>>(x, tw, tb, pw, pb, gw, gb);
    cvtT_kernel<<<2048, 256>>>();
    trP_kernel<<<dim3(128, 4, NB), dim3(32, 8)>>>();
    scores_mma_kernel<<<dim3(32, 32, NB), 256, SC_BYTES>>>();
    zreduce_kernel<<<64, 256>>>();
    gscale_kernel<<<dim3(128, 4, NB), dim3(32, 8)>>>();
    y_mma_kernel<<<dim3(64, NB), 256, Y_BYTES>>>();
    out_kernel<<<dim3(32, 2, NB), 256>>>(x, Ww, Wb, out);
}

// round 14
// speedup vs baseline: 1.5056x; 1.5056x over previous
#include <cuda_runtime.h>
#include <cuda_bf16.h>
#include <math.h>
#include <stdint.h>

#define CB  128
#define CIN 256
#define NSP 4096
#define NB  4

typedef unsigned long long u64;

// ===================== helpers =====================
__device__ __forceinline__ uint32_t smem_to_u32(const void* p) {
    uint32_t a;
    asm("{ .reg .u64 t; cvta.to.shared.u64 t, %1; cvt.u32.u64 %0, t; }" : "=r"(a) : "l"(p));
    return a;
}
__device__ __forceinline__ void ldsm4(uint32_t* r, uint32_t a) {
    asm volatile("ldmatrix.sync.aligned.m8n8.x4.shared.b16 {%0,%1,%2,%3}, [%4];"
        : "=r"(r[0]), "=r"(r[1]), "=r"(r[2]), "=r"(r[3]) : "r"(a));
}
__device__ __forceinline__ void mma16816(float* c, const uint32_t* a, uint32_t b0, uint32_t b1) {
    asm volatile("mma.sync.aligned.m16n8k16.row.col.f32.bf16.bf16.f32 "
        "{%0,%1,%2,%3}, {%4,%5,%6,%7}, {%8,%9}, {%0,%1,%2,%3};"
        : "+f"(c[0]), "+f"(c[1]), "+f"(c[2]), "+f"(c[3])
        : "r"(a[0]), "r"(a[1]), "r"(a[2]), "r"(a[3]), "r"(b0), "r"(b1));
}
#define CP_ASYNC16(dst, src) \
    asm volatile("cp.async.cg.shared.global [%0], [%1], 16;" :: "r"(dst), "l"(src))
#define CP_COMMIT()  asm volatile("cp.async.commit_group;" ::: "memory")
#define CP_WAIT1()   asm volatile("cp.async.wait_group 1;" ::: "memory")
#define CP_WAIT0()   asm volatile("cp.async.wait_group 0;" ::: "memory")

// FFMA2 helpers (SIMT kernels)
__device__ __forceinline__ u64 pk2(float a, float b) {
    u64 r; asm("mov.b64 %0, {%1, %2};" : "=l"(r) : "f"(a), "f"(b)); return r;
}
__device__ __forceinline__ void upk2(u64 v, float& a, float& b) {
    asm("mov.b64 {%0, %1}, %2;" : "=f"(a), "=f"(b) : "l"(v));
}
__device__ __forceinline__ u64 fma2(u64 a, u64 b, u64 c) {
    u64 d; asm("fma.rn.f32x2 %0, %1, %2, %3;" : "=l"(d) : "l"(a), "l"(b), "l"(c)); return d;
}

// ===================== scratch =====================
__device__ float g_T[(size_t)NB * CB * NSP];
__device__ float g_P[(size_t)NB * CB * NSP];
__device__ float g_G[(size_t)NB * CB * NSP];
__device__ float g_Y[(size_t)NB * CB * NSP];
__device__ __nv_bfloat16 g_Shi[(size_t)NB * NSP * NSP];  // expS hi
__device__ __nv_bfloat16 g_Slo[(size_t)NB * NSP * NSP];  // expS lo
__device__ float g_Zp[NB * 32 * NSP];
__device__ float g_Zr[NB * NSP];
__device__ __nv_bfloat16 g_Thi[(size_t)NB * NSP * CB];
__device__ __nv_bfloat16 g_Tlo[(size_t)NB * NSP * CB];
__device__ __nv_bfloat16 g_Phi[(size_t)NB * NSP * CB];
__device__ __nv_bfloat16 g_Plo[(size_t)NB * NSP * CB];
__device__ __nv_bfloat16 g_Ghi[(size_t)NB * CB * NSP];  // (c,m) * 1/Z
__device__ __nv_bfloat16 g_Glo[(size_t)NB * CB * NSP];

// scores smem: 272B row stride (conflict-free ldsm)
#define SC_AHI 0
#define SC_ALO 34816
#define SC_BHI 69632
#define SC_BLO 139264
#define SC_BYTES 208896

// y smem: double-buffered 64-wide K chunks, 144B row stride
#define YB_TILE 18432            // 128 rows * 144B
#define YB_BUF  73728            // 4 tiles (Ahi, Alo, Bhi, Blo)
#define Y_BYTES 147456

// ---------------------------------------------------------------------------
// Kernel 1: T/P/G 1x1 convs (SIMT FFMA2). grid (32,1,12)
// ---------------------------------------------------------------------------
__global__ __launch_bounds__(256, 2) void conv_tpg_kernel(
    const float* __restrict__ x,
    const float* __restrict__ tw, const float* __restrict__ tbias,
    const float* __restrict__ pw, const float* __restrict__ pbias,
    const float* __restrict__ gw, const float* __restrict__ gbias)
{
    int z = blockIdx.z;
    int b = z / 3, mat = z - b * 3;
    const float* W    = (mat == 0) ? tw    : (mat == 1) ? pw    : gw;
    const float* bias = (mat == 0) ? tbias : (mat == 1) ? pbias : gbias;
    float* Cout = ((mat == 0) ? g_T : (mat == 1) ? g_P : g_G) + (size_t)b * CB * NSP;
    const float* Bx = x + (size_t)b * CIN * NSP;

    __shared__ __align__(16) float As[8][132];
    __shared__ __align__(16) float Bs[8][128];
    int tid  = threadIdx.x;
    int aRow = tid >> 1, aCol = (tid & 1) << 2;
    int bRow = tid >> 5, bCol = (tid & 31) << 2;
    int ty = tid >> 4, tx = tid & 15;
    int colBase = blockIdx.x << 7;

    u64 acc[8][4];
#pragma unroll
    for (int i = 0; i < 8; i++)
#pragma unroll
        for (int jp = 0; jp < 4; jp++) acc[i][jp] = pk2(0.f, 0.f);

    for (int k0 = 0; k0 < CIN; k0 += 8) {
        float4 av = *(const float4*)(W + (size_t)aRow * CIN + k0 + aCol);
        As[aCol + 0][aRow] = av.x;
        As[aCol + 1][aRow] = av.y;
        As[aCol + 2][aRow] = av.z;
        As[aCol + 3][aRow] = av.w;
        *(float4*)&Bs[bRow][bCol] =
            *(const float4*)(Bx + (size_t)(k0 + bRow) * NSP + colBase + bCol);
        __syncthreads();
#pragma unroll
        for (int k = 0; k < 8; k++) {
            float ra[8];
            *(float4*)(ra)     = *(const float4*)&As[k][ty << 2];
            *(float4*)(ra + 4) = *(const float4*)&As[k][64 + (ty << 2)];
            const u64* bp0 = (const u64*)&Bs[k][tx << 2];
            const u64* bp1 = (const u64*)&Bs[k][64 + (tx << 2)];
            u64 rb[4] = {bp0[0], bp0[1], bp1[0], bp1[1]};
#pragma unroll
            for (int i = 0; i < 8; i++) {
                u64 aa = pk2(ra[i], ra[i]);
#pragma unroll
                for (int jp = 0; jp < 4; jp++)
                    acc[i][jp] = fma2(aa, rb[jp], acc[i][jp]);
            }
        }
        __syncthreads();
    }
#pragma unroll
    for (int i = 0; i < 8; i++) {
        int row = ((i >> 2) << 6) + (ty << 2) + (i & 3);
        float bv = bias[row];
#pragma unroll
        for (int jh = 0; jh < 2; jh++) {
            float4 v;
            upk2(acc[i][2 * jh],     v.x, v.y);
            upk2(acc[i][2 * jh + 1], v.z, v.w);
            v.x += bv; v.y += bv; v.z += bv; v.w += bv;
            *(float4*)(Cout + (size_t)row * NSP + colBase + (jh << 6) + (tx << 2)) = v;
        }
    }
}

// ---------------------------------------------------------------------------
// Kernel 2a: T -> bf16 hi/lo. grid 2048, 256 thr
// ---------------------------------------------------------------------------
__global__ __launch_bounds__(256) void cvtT_kernel()
{
    size_t i = ((size_t)blockIdx.x * 256 + threadIdx.x) * 4;
    float4 v = *(const float4*)(g_T + i);
    __nv_bfloat16 hx = __float2bfloat16_rn(v.x), hy = __float2bfloat16_rn(v.y);
    __nv_bfloat16 hz = __float2bfloat16_rn(v.z), hw = __float2bfloat16_rn(v.w);
    __nv_bfloat162 h01(hx, hy), h23(hz, hw);
    __nv_bfloat162 l01(__float2bfloat16_rn(v.x - __bfloat162float(hx)),
                       __float2bfloat16_rn(v.y - __bfloat162float(hy)));
    __nv_bfloat162 l23(__float2bfloat16_rn(v.z - __bfloat162float(hz)),
                       __float2bfloat16_rn(v.w - __bfloat162float(hw)));
    *(uint2*)(g_Thi + i) = make_uint2(*(uint32_t*)&h01, *(uint32_t*)&h23);
    *(uint2*)(g_Tlo + i) = make_uint2(*(uint32_t*)&l01, *(uint32_t*)&l23);
}

// ---------------------------------------------------------------------------
// Kernel 2b: P (128,4096) -> Pt (4096,128) bf16 hi/lo. grid (128,4,NB), blk (32,8)
// ---------------------------------------------------------------------------
__global__ __launch_bounds__(256) void trP_kernel()
{
    int b = blockIdx.z;
    const float* P = g_P + (size_t)b * CB * NSP;
    __shared__ float sm[32][33];
    int tx = threadIdx.x, ty = threadIdx.y;
    int n0 = blockIdx.x << 5, k0 = blockIdx.y << 5;
#pragma unroll
    for (int i = 0; i < 4; i++)
        sm[ty + i * 8][tx] = P[(size_t)(k0 + ty + i * 8) * NSP + n0 + tx];
    __syncthreads();
#pragma unroll
    for (int i = 0; i < 4; i++) {
        int n = n0 + ty + i * 8, k = k0 + tx;
        float v = sm[tx][ty + i * 8];
        __nv_bfloat16 h = __float2bfloat16_rn(v);
        g_Phi[((size_t)b * NSP + n) * CB + k] = h;
        g_Plo[((size_t)b * NSP + n) * CB + k] = __float2bfloat16_rn(v - __bfloat162float(h));
    }
}

// ---------------------------------------------------------------------------
// Kernel 3: expS tile (128x256) = exp(T @ Pt^T), written as bf16 hi/lo.
// grid (16 coltile, 32 rowtile, NB), 512 thr (16 warps, 32x64 warp tiles)
// ---------------------------------------------------------------------------
__global__ __launch_bounds__(512, 1) void scores_mma_kernel()
{
    extern __shared__ __align__(16) char smem[];
    const int tid = threadIdx.x;
    const int wid = tid >> 5, lane = tid & 31;
    const int b = blockIdx.z;
    const int rowBase = blockIdx.y << 7;
    const int colBase = blockIdx.x << 8;   // 256-wide col tiles

    {   // stage A (128 rows x 128 k) hi/lo and B (256 rows x 128 k) hi/lo,
        // row stride 272B; 16 granules of 16B per row.
        const __nv_bfloat16* Ah = g_Thi + ((size_t)b * NSP + rowBase) * CB;
        const __nv_bfloat16* Al = g_Tlo + ((size_t)b * NSP + rowBase) * CB;
        const __nv_bfloat16* Bh = g_Phi + ((size_t)b * NSP + colBase) * CB;
        const __nv_bfloat16* Bl = g_Plo + ((size_t)b * NSP + colBase) * CB;
#pragma unroll
        for (int i = 0; i < 4; i++) {
            int gid = tid + i * 512;           // A: 2048 granules
            int r = gid >> 4, g16 = gid & 15;
            size_t gi = (size_t)r * CB + g16 * 8;
            uint32_t so = r * 272 + g16 * 16;
            *(uint4*)(smem + SC_AHI + so) = *(const uint4*)(Ah + gi);
            *(uint4*)(smem + SC_ALO + so) = *(const uint4*)(Al + gi);
        }
#pragma unroll
        for (int i = 0; i < 8; i++) {
            int gid = tid + i * 512;           // B: 4096 granules
            int r = gid >> 4, g16 = gid & 15;
            size_t gi = (size_t)r * CB + g16 * 8;
            uint32_t so = r * 272 + g16 * 16;
            *(uint4*)(smem + SC_BHI + so) = *(const uint4*)(Bh + gi);
            *(uint4*)(smem + SC_BLO + so) = *(const uint4*)(Bl + gi);
        }
    }
    __syncthreads();

    const uint32_t sb = smem_to_u32(smem);
    const int mrow = (wid & 3) * 32, ncol = (wid >> 2) * 64;
    const int aR = lane & 15, aK = (lane >> 4) * 8;
    const int bN = (lane & 7) + ((lane >> 4) << 3), bK = ((lane >> 3) & 1) * 8;

    float acc[2][8][4];
#pragma unroll
    for (int mi = 0; mi < 2; mi++)
#pragma unroll
        for (int n = 0; n < 8; n++)
#pragma unroll
            for (int q = 0; q < 4; q++) acc[mi][n][q] = 0.f;

#pragma unroll
    for (int ks = 0; ks < 8; ks++) {
        int k0 = ks * 16;
        uint32_t ahi[2][4], alo[2][4], bhi[4][4], blo[4][4];
#pragma unroll
        for (int mi = 0; mi < 2; mi++) {
            uint32_t ad = sb + SC_AHI + (mrow + mi * 16 + aR) * 272 + (k0 + aK) * 2;
            ldsm4(ahi[mi], ad);
            ldsm4(alo[mi], ad + (SC_ALO - SC_AHI));
        }
#pragma unroll
        for (int nj = 0; nj < 4; nj++) {
            uint32_t bd = sb + SC_BHI + (ncol + nj * 16 + bN) * 272 + (k0 + bK) * 2;
            ldsm4(bhi[nj], bd);
            ldsm4(blo[nj], bd + (SC_BLO - SC_BHI));
        }
#pragma unroll
        for (int nj = 0; nj < 4; nj++)
#pragma unroll
            for (int mi = 0; mi < 2; mi++) {
                mma16816(acc[mi][nj * 2],     ahi[mi], bhi[nj][0], bhi[nj][1]);
                mma16816(acc[mi][nj * 2 + 1], ahi[mi], bhi[nj][2], bhi[nj][3]);
            }
#pragma unroll
        for (int nj = 0; nj < 4; nj++)
#pragma unroll
            for (int mi = 0; mi < 2; mi++) {
                mma16816(acc[mi][nj * 2],     ahi[mi], blo[nj][0], blo[nj][1]);
                mma16816(acc[mi][nj * 2 + 1], ahi[mi], blo[nj][2], blo[nj][3]);
            }
#pragma unroll
        for (int nj = 0; nj < 4; nj++)
#pragma unroll
            for (int mi = 0; mi < 2; mi++) {
                mma16816(acc[mi][nj * 2],     alo[mi], bhi[nj][0], bhi[nj][1]);
                mma16816(acc[mi][nj * 2 + 1], alo[mi], bhi[nj][2], bhi[nj][3]);
            }
    }
    __syncthreads();   // tiles done; reuse smem for column reduction

    float (*sRed)[257] = (float(*)[257])smem;
    __nv_bfloat16* Shi = g_Shi + (size_t)b * NSP * NSP;
    __nv_bfloat16* Slo = g_Slo + (size_t)b * NSP * NSP;
    const int g = lane >> 2, tig = lane & 3;
#pragma unroll
    for (int mi = 0; mi < 2; mi++)
#pragma unroll
        for (int rr = 0; rr < 2; rr++) {
            int rowl = mrow + mi * 16 + g + rr * 8;
            size_t rbase = (size_t)(rowBase + rowl) * NSP + colBase;
#pragma unroll
            for (int ni = 0; ni < 8; ni++) {
                int coll = ncol + ni * 8 + tig * 2;
                float e0 = __expf(acc[mi][ni][rr * 2 + 0]);
                float e1 = __expf(acc[mi][ni][rr * 2 + 1]);
                __nv_bfloat16 h0 = __float2bfloat16_rn(e0);
                __nv_bfloat16 h1 = __float2bfloat16_rn(e1);
                __nv_bfloat162 hp(h0, h1);
                __nv_bfloat162 lp(__float2bfloat16_rn(e0 - __bfloat162float(h0)),
                                  __float2bfloat16_rn(e1 - __bfloat162float(h1)));
                *(uint32_t*)(Shi + rbase + coll) = *(uint32_t*)&hp;
                *(uint32_t*)(Slo + rbase + coll) = *(uint32_t*)&lp;
                sRed[rowl][coll]     = e0;
                sRed[rowl][coll + 1] = e1;
            }
        }
    __syncthreads();
    if (tid < 256) {
        float s = 0.f;
#pragma unroll 16
        for (int r = 0; r < 128; r++) s += sRed[r][tid];
        g_Zp[(b * 32 + blockIdx.y) * NSP + colBase + tid] = s;
    }
}

// ---------------------------------------------------------------------------
// Kernel 4: 1/Z per column. grid 64, 256 thr
// ---------------------------------------------------------------------------
__global__ __launch_bounds__(256) void zreduce_kernel()
{
    int t = blockIdx.x * 256 + threadIdx.x;
    int b = t >> 12, m = t & (NSP - 1);
    float s = 0.f;
#pragma unroll 8
    for (int r = 0; r < 32; r++) s += g_Zp[(b * 32 + r) * NSP + m];
    g_Zr[t] = 1.0f / s;
}

// ---------------------------------------------------------------------------
// Kernel 5: Gt'(c,m) = Gview[m][c] * Zr[m], bf16 hi/lo. grid (128,4,NB), blk (32,8)
// ---------------------------------------------------------------------------
__global__ __launch_bounds__(256) void gscale_kernel()
{
    int b = blockIdx.z;
    const float* Gf = g_G + (size_t)b * CB * NSP;
    const float* Zr = g_Zr + b * NSP;
    __shared__ float sm[32][33];
    int tx = threadIdx.x, ty = threadIdx.y;
    int m0 = blockIdx.x << 5, c0 = blockIdx.y << 5;
#pragma unroll
    for (int i = 0; i < 4; i++) {
        int m = m0 + ty + i * 8;
        sm[ty + i * 8][tx] = Gf[(size_t)m * CB + c0 + tx] * Zr[m];
    }
    __syncthreads();
#pragma unroll
    for (int i = 0; i < 4; i++) {
        int c = c0 + ty + i * 8, m = m0 + tx;
        float v = sm[tx][ty + i * 8];
        __nv_bfloat16 h = __float2bfloat16_rn(v);
        g_Ghi[((size_t)b * CB + c) * NSP + m] = h;
        g_Glo[((size_t)b * CB + c) * NSP + m] = __float2bfloat16_rn(v - __bfloat162float(h));
    }
}

// ---------------------------------------------------------------------------
// Kernel 6: Y(128x128) = expS @ (Gt')^T. 512 thr, 16 warps (32x32 warp tiles),
// K=4096 in 64-wide chunks, cp.async double-buffered. grid (32, NB) = 128 CTAs.
// ---------------------------------------------------------------------------
__global__ __launch_bounds__(512, 1) void y_mma_kernel()
{
    extern __shared__ __align__(16) char smem[];
    const int tid = threadIdx.x;
    const int wid = tid >> 5, lane = tid & 31;
    const int b = blockIdx.y;
    const int rowBase = blockIdx.x << 7;

    const uint32_t sb = smem_to_u32(smem);
    const int mrow = (wid & 3) * 32, ncol = (wid >> 2) * 32;
    const int aR = lane & 15, aK = (lane >> 4) * 8;
    const int bN = (lane & 7) + ((lane >> 4) << 3), bK = ((lane >> 3) & 1) * 8;

    const __nv_bfloat16* Sh = g_Shi + (size_t)b * NSP * NSP;
    const __nv_bfloat16* Sl = g_Slo + (size_t)b * NSP * NSP;
    const __nv_bfloat16* Gh = g_Ghi + (size_t)b * CB * NSP;
    const __nv_bfloat16* Gl = g_Glo + (size_t)b * CB * NSP;

    const int arow = tid >> 3, ag = tid & 7;     // A: rows arow, arow+64; 8 granules/row
    const int brow = tid >> 2, bg = tid & 3;     // B: 128 rows, granules bg and bg+4

    // acc[mi][n4][4]: mi 2 (16-row halves), n4 = nj*2+h (4 8-col groups)
    float acc[2][4][4];
#pragma unroll
    for (int mi = 0; mi < 2; mi++)
#pragma unroll
        for (int n = 0; n < 4; n++)
#pragma unroll
            for (int q = 0; q < 4; q++) acc[mi][n][q] = 0.f;

#define Y_STAGE(kt, s) do { \
    int kg = (kt) << 6; \
    uint32_t bufs = sb + (s) * YB_BUF; \
    _Pragma("unroll") \
    for (int i = 0; i < 2; i++) { \
        int r = arow + i * 64; \
        uint32_t so = bufs + r * 144 + ag * 16; \
        CP_ASYNC16(so,            Sh + (size_t)(rowBase + r) * NSP + kg + ag * 8); \
        CP_ASYNC16(so + YB_TILE,  Sl + (size_t)(rowBase + r) * NSP + kg + ag * 8); \
    } \
    { \
        uint32_t so = bufs + 2 * YB_TILE + brow * 144 + bg * 16; \
        const __nv_bfloat16* gh = Gh + (size_t)brow * NSP + kg + bg * 8; \
        const __nv_bfloat16* gl = Gl + (size_t)brow * NSP + kg + bg * 8; \
        CP_ASYNC16(so,                 gh); \
        CP_ASYNC16(so + YB_TILE,       gl); \
        CP_ASYNC16(so + 64,            gh + 32); \
        CP_ASYNC16(so + YB_TILE + 64,  gl + 32); \
    } \
    CP_COMMIT(); \
} while (0)

    Y_STAGE(0, 0);

    for (int kt = 0; kt < 64; kt++) {
        if (kt < 63) { Y_STAGE(kt + 1, (kt + 1) & 1); CP_WAIT1(); }
        else         { CP_WAIT0(); }
        __syncthreads();

        uint32_t bufs = sb + (kt & 1) * YB_BUF;
#pragma unroll
        for (int ks = 0; ks < 4; ks++) {
            int k0 = ks * 16;
            uint32_t ahi[2][4], alo[2][4], bhi[2][4], blo[2][4];
#pragma unroll
            for (int mi = 0; mi < 2; mi++) {
                uint32_t ad = bufs + (mrow + mi * 16 + aR) * 144 + (k0 + aK) * 2;
                ldsm4(ahi[mi], ad);
                ldsm4(alo[mi], ad + YB_TILE);
            }
#pragma unroll
            for (int nj = 0; nj < 2; nj++) {
                uint32_t bd = bufs + 2 * YB_TILE + (ncol + nj * 16 + bN) * 144 + (k0 + bK) * 2;
                ldsm4(bhi[nj], bd);
                ldsm4(blo[nj], bd + YB_TILE);
            }
#pragma unroll
            for (int mi = 0; mi < 2; mi++)
#pragma unroll
                for (int nj = 0; nj < 2; nj++) {
                    mma16816(acc[mi][nj * 2],     ahi[mi], bhi[nj][0], bhi[nj][1]);
                    mma16816(acc[mi][nj * 2 + 1], ahi[mi], bhi[nj][2], bhi[nj][3]);
                }
#pragma unroll
            for (int mi = 0; mi < 2; mi++)
#pragma unroll
                for (int nj = 0; nj < 2; nj++) {
                    mma16816(acc[mi][nj * 2],     ahi[mi], blo[nj][0], blo[nj][1]);
                    mma16816(acc[mi][nj * 2 + 1], ahi[mi], blo[nj][2], blo[nj][3]);
                }
#pragma unroll
            for (int mi = 0; mi < 2; mi++)
#pragma unroll
                for (int nj = 0; nj < 2; nj++) {
                    mma16816(acc[mi][nj * 2],     alo[mi], bhi[nj][0], bhi[nj][1]);
                    mma16816(acc[mi][nj * 2 + 1], alo[mi], bhi[nj][2], bhi[nj][3]);
                }
        }
        __syncthreads();
    }

    const int g = lane >> 2, tig = lane & 3;
#pragma unroll
    for (int mi = 0; mi < 2; mi++)
#pragma unroll
        for (int rr = 0; rr < 2; rr++) {
            int row = rowBase + mrow + mi * 16 + g + rr * 8;
            float* yrow = g_Y + ((size_t)b * NSP + row) * CB;
#pragma unroll
            for (int ni = 0; ni < 4; ni++) {
                int col = ncol + ni * 8 + tig * 2;
                *(float2*)(yrow + col) =
                    make_float2(acc[mi][ni][rr * 2], acc[mi][ni][rr * 2 + 1]);
            }
        }
#undef Y_STAGE
}

// ---------------------------------------------------------------------------
// Kernel 7: Out = W_w @ Yview + W_b + x (SIMT FFMA2). grid (32,2,NB)
// ---------------------------------------------------------------------------
__global__ __launch_bounds__(256, 2) void out_kernel(
    const float* __restrict__ x,
    const float* __restrict__ Ww, const float* __restrict__ Wb,
    float* __restrict__ out)
{
    int b = blockIdx.z;
    const float* Byc = g_Y + (size_t)b * CB * NSP;
    const float* xb  = x + (size_t)b * CIN * NSP;
    float* Cb_ = out + (size_t)b * CIN * NSP;

    __shared__ __align__(16) float As[8][132];
    __shared__ __align__(16) float Bs[8][128];
    int tid  = threadIdx.x;
    int aRow = tid >> 1, aCol = (tid & 1) << 2;
    int bRow = tid >> 5, bCol = (tid & 31) << 2;
    int ty = tid >> 4, tx = tid & 15;
    int rowBase = blockIdx.y << 7;
    int colBase = blockIdx.x << 7;

    u64 acc[8][4];
#pragma unroll
    for (int i = 0; i < 8; i++)
#pragma unroll
        for (int jp = 0; jp < 4; jp++) acc[i][jp] = pk2(0.f, 0.f);

    for (int k0 = 0; k0 < CB; k0 += 8) {
        float4 av = *(const float4*)(Ww + (size_t)(rowBase + aRow) * CB + k0 + aCol);
        As[aCol + 0][aRow] = av.x;
        As[aCol + 1][aRow] = av.y;
        As[aCol + 2][aRow] = av.z;
        As[aCol + 3][aRow] = av.w;
        *(float4*)&Bs[bRow][bCol] =
            *(const float4*)(Byc + (size_t)(k0 + bRow) * NSP + colBase + bCol);
        __syncthreads();
#pragma unroll
        for (int k = 0; k < 8; k++) {
            float ra[8];
            *(float4*)(ra)     = *(const float4*)&As[k][ty << 2];
            *(float4*)(ra + 4) = *(const float4*)&As[k][64 + (ty << 2)];
            const u64* bp0 = (const u64*)&Bs[k][tx << 2];
            const u64* bp1 = (const u64*)&Bs[k][64 + (tx << 2)];
            u64 rb[4] = {bp0[0], bp0[1], bp1[0], bp1[1]};
#pragma unroll
            for (int i = 0; i < 8; i++) {
                u64 aa = pk2(ra[i], ra[i]);
#pragma unroll
                for (int jp = 0; jp < 4; jp++)
                    acc[i][jp] = fma2(aa, rb[jp], acc[i][jp]);
            }
        }
        __syncthreads();
    }
#pragma unroll
    for (int i = 0; i < 8; i++) {
        int row = rowBase + ((i >> 2) << 6) + (ty << 2) + (i & 3);
        float bv = Wb[row];
#pragma unroll
        for (int jh = 0; jh < 2; jh++) {
            int col = colBase + (jh << 6) + (tx << 2);
            float4 xv = *(const float4*)(xb + (size_t)row * NSP + col);
            float4 v;
            upk2(acc[i][2 * jh],     v.x, v.y);
            upk2(acc[i][2 * jh + 1], v.z, v.w);
            v.x += bv + xv.x; v.y += bv + xv.y;
            v.z += bv + xv.z; v.w += bv + xv.w;
            *(float4*)(Cb_ + (size_t)row * NSP + col) = v;
        }
    }
}

// ---------------------------------------------------------------------------
extern "C" void kernel_launch(void* const* d_in, const int* in_sizes, int n_in,
                              void* d_out, int out_size)
{
    const float* x  = (const float*)d_in[0];
    const float* tw = (const float*)d_in[1];
    const float* tb = (const float*)d_in[2];
    const float* pw = (const float*)d_in[3];
    const float* pb = (const float*)d_in[4];
    const float* gw = (const float*)d_in[5];
    const float* gb = (const float*)d_in[6];
    const float* Ww = (const float*)d_in[7];
    const float* Wb = (const float*)d_in[8];
    float* out = (float*)d_out;

    cudaFuncSetAttribute(scores_mma_kernel, cudaFuncAttributeMaxDynamicSharedMemorySize, SC_BYTES);
    cudaFuncSetAttribute(y_mma_kernel, cudaFuncAttributeMaxDynamicSharedMemorySize, Y_BYTES);

    conv_tpg_kernel<<<dim3(32, 1, 12), 256>>>(x, tw, tb, pw, pb, gw, gb);
    cvtT_kernel<<<2048, 256>>>();
    trP_kernel<<<dim3(128, 4, NB), dim3(32, 8)>>>();
    scores_mma_kernel<<<dim3(16, 32, NB), 512, SC_BYTES>>>();
    zreduce_kernel<<<64, 256>>>();
    gscale_kernel<<<dim3(128, 4, NB), dim3(32, 8)>>>();
    y_mma_kernel<<<dim3(32, NB), 512, Y_BYTES>>>();
    out_kernel<<<dim3(32, 2, NB), 256>>>(x, Ww, Wb, out);
}

// round 16
// speedup vs baseline: 1.6370x; 1.0873x over previous
#include <cuda_runtime.h>
#include <cuda_bf16.h>
#include <math.h>
#include <stdint.h>

#define CB  128
#define CIN 256
#define NSP 4096
#define NB  4

typedef unsigned long long u64;

// ===================== helpers =====================
__device__ __forceinline__ uint32_t smem_to_u32(const void* p) {
    uint32_t a;
    asm("{ .reg .u64 t; cvta.to.shared.u64 t, %1; cvt.u32.u64 %0, t; }" : "=r"(a) : "l"(p));
    return a;
}
__device__ __forceinline__ void ldsm4(uint32_t* r, uint32_t a) {
    asm volatile("ldmatrix.sync.aligned.m8n8.x4.shared.b16 {%0,%1,%2,%3}, [%4];"
        : "=r"(r[0]), "=r"(r[1]), "=r"(r[2]), "=r"(r[3]) : "r"(a));
}
__device__ __forceinline__ void mma16816(float* c, const uint32_t* a, uint32_t b0, uint32_t b1) {
    asm volatile("mma.sync.aligned.m16n8k16.row.col.f32.bf16.bf16.f32 "
        "{%0,%1,%2,%3}, {%4,%5,%6,%7}, {%8,%9}, {%0,%1,%2,%3};"
        : "+f"(c[0]), "+f"(c[1]), "+f"(c[2]), "+f"(c[3])
        : "r"(a[0]), "r"(a[1]), "r"(a[2]), "r"(a[3]), "r"(b0), "r"(b1));
}
#define CP_ASYNC16(dst, src) \
    asm volatile("cp.async.cg.shared.global [%0], [%1], 16;" :: "r"(dst), "l"(src))
#define CP_COMMIT()  asm volatile("cp.async.commit_group;" ::: "memory")
#define CP_WAIT2()   asm volatile("cp.async.wait_group 2;" ::: "memory")
#define CP_WAIT1()   asm volatile("cp.async.wait_group 1;" ::: "memory")
#define CP_WAIT0()   asm volatile("cp.async.wait_group 0;" ::: "memory")

// FFMA2 helpers (SIMT kernels)
__device__ __forceinline__ u64 pk2(float a, float b) {
    u64 r; asm("mov.b64 %0, {%1, %2};" : "=l"(r) : "f"(a), "f"(b)); return r;
}
__device__ __forceinline__ void upk2(u64 v, float& a, float& b) {
    asm("mov.b64 {%0, %1}, %2;" : "=f"(a), "=f"(b) : "l"(v));
}
__device__ __forceinline__ u64 fma2(u64 a, u64 b, u64 c) {
    u64 d; asm("fma.rn.f32x2 %0, %1, %2, %3;" : "=l"(d) : "l"(a), "l"(b), "l"(c)); return d;
}

// ===================== scratch =====================
__device__ float g_T[(size_t)NB * CB * NSP];
__device__ float g_P[(size_t)NB * CB * NSP];
__device__ float g_G[(size_t)NB * CB * NSP];
__device__ float g_Y[(size_t)NB * CB * NSP];
__device__ __nv_bfloat16 g_Shi[(size_t)NB * NSP * NSP];  // expS hi
__device__ __nv_bfloat16 g_Slo[(size_t)NB * NSP * NSP];  // expS lo
__device__ float g_Zr[NB * NSP];
__device__ __nv_bfloat16 g_Thi[(size_t)NB * NSP * CB];
__device__ __nv_bfloat16 g_Tlo[(size_t)NB * NSP * CB];
__device__ __nv_bfloat16 g_Phi[(size_t)NB * NSP * CB];
__device__ __nv_bfloat16 g_Plo[(size_t)NB * NSP * CB];
__device__ __nv_bfloat16 g_Ghi[(size_t)NB * CB * NSP];  // (c,m) * 1/Z
__device__ __nv_bfloat16 g_Glo[(size_t)NB * CB * NSP];

// scores smem: persistent column-strip. 272B row stride (conflict-free ldsm).
// [0, 34816)        B hi (128 rows of Pt)
// [34816, 69632)    B lo
// [69632 + s*69632) A double buffers s=0,1: AHI then ALO (34816 each)
#define SP_BHI 0
#define SP_BLO 34816
#define SP_A0  69632
#define SP_ATL 34816          // ALO offset within an A buffer
#define SP_ABUF 69632         // size of one A buffer (hi+lo)
#define SC_BYTES 208896

// y smem: triple-buffered 64-wide K chunks, 144B row stride
#define YB_TILE 18432            // 128 rows * 144B
#define YB_BUF  73728            // 4 tiles (Ahi, Alo, Bhi, Blo)
#define Y_BYTES 221184           // 3 buffers

// ---------------------------------------------------------------------------
// Kernel 1: T/P/G 1x1 convs (SIMT FFMA2). grid (32,1,12)
// ---------------------------------------------------------------------------
__global__ __launch_bounds__(256, 2) void conv_tpg_kernel(
    const float* __restrict__ x,
    const float* __restrict__ tw, const float* __restrict__ tbias,
    const float* __restrict__ pw, const float* __restrict__ pbias,
    const float* __restrict__ gw, const float* __restrict__ gbias)
{
    int z = blockIdx.z;
    int b = z / 3, mat = z - b * 3;
    const float* W    = (mat == 0) ? tw    : (mat == 1) ? pw    : gw;
    const float* bias = (mat == 0) ? tbias : (mat == 1) ? pbias : gbias;
    float* Cout = ((mat == 0) ? g_T : (mat == 1) ? g_P : g_G) + (size_t)b * CB * NSP;
    const float* Bx = x + (size_t)b * CIN * NSP;

    __shared__ __align__(16) float As[8][132];
    __shared__ __align__(16) float Bs[8][128];
    int tid  = threadIdx.x;
    int aRow = tid >> 1, aCol = (tid & 1) << 2;
    int bRow = tid >> 5, bCol = (tid & 31) << 2;
    int ty = tid >> 4, tx = tid & 15;
    int colBase = blockIdx.x << 7;

    u64 acc[8][4];
#pragma unroll
    for (int i = 0; i < 8; i++)
#pragma unroll
        for (int jp = 0; jp < 4; jp++) acc[i][jp] = pk2(0.f, 0.f);

    for (int k0 = 0; k0 < CIN; k0 += 8) {
        float4 av = *(const float4*)(W + (size_t)aRow * CIN + k0 + aCol);
        As[aCol + 0][aRow] = av.x;
        As[aCol + 1][aRow] = av.y;
        As[aCol + 2][aRow] = av.z;
        As[aCol + 3][aRow] = av.w;
        *(float4*)&Bs[bRow][bCol] =
            *(const float4*)(Bx + (size_t)(k0 + bRow) * NSP + colBase + bCol);
        __syncthreads();
#pragma unroll
        for (int k = 0; k < 8; k++) {
            float ra[8];
            *(float4*)(ra)     = *(const float4*)&As[k][ty << 2];
            *(float4*)(ra + 4) = *(const float4*)&As[k][64 + (ty << 2)];
            const u64* bp0 = (const u64*)&Bs[k][tx << 2];
            const u64* bp1 = (const u64*)&Bs[k][64 + (tx << 2)];
            u64 rb[4] = {bp0[0], bp0[1], bp1[0], bp1[1]};
#pragma unroll
            for (int i = 0; i < 8; i++) {
                u64 aa = pk2(ra[i], ra[i]);
#pragma unroll
                for (int jp = 0; jp < 4; jp++)
                    acc[i][jp] = fma2(aa, rb[jp], acc[i][jp]);
            }
        }
        __syncthreads();
    }
#pragma unroll
    for (int i = 0; i < 8; i++) {
        int row = ((i >> 2) << 6) + (ty << 2) + (i & 3);
        float bv = bias[row];
#pragma unroll
        for (int jh = 0; jh < 2; jh++) {
            float4 v;
            upk2(acc[i][2 * jh],     v.x, v.y);
            upk2(acc[i][2 * jh + 1], v.z, v.w);
            v.x += bv; v.y += bv; v.z += bv; v.w += bv;
            *(float4*)(Cout + (size_t)row * NSP + colBase + (jh << 6) + (tx << 2)) = v;
        }
    }
}

// ---------------------------------------------------------------------------
// Kernel 2a: T -> bf16 hi/lo. grid 2048, 256 thr
// ---------------------------------------------------------------------------
__global__ __launch_bounds__(256) void cvtT_kernel()
{
    size_t i = ((size_t)blockIdx.x * 256 + threadIdx.x) * 4;
    float4 v = *(const float4*)(g_T + i);
    __nv_bfloat16 hx = __float2bfloat16_rn(v.x), hy = __float2bfloat16_rn(v.y);
    __nv_bfloat16 hz = __float2bfloat16_rn(v.z), hw = __float2bfloat16_rn(v.w);
    __nv_bfloat162 h01(hx, hy), h23(hz, hw);
    __nv_bfloat162 l01(__float2bfloat16_rn(v.x - __bfloat162float(hx)),
                       __float2bfloat16_rn(v.y - __bfloat162float(hy)));
    __nv_bfloat162 l23(__float2bfloat16_rn(v.z - __bfloat162float(hz)),
                       __float2bfloat16_rn(v.w - __bfloat162float(hw)));
    *(uint2*)(g_Thi + i) = make_uint2(*(uint32_t*)&h01, *(uint32_t*)&h23);
    *(uint2*)(g_Tlo + i) = make_uint2(*(uint32_t*)&l01, *(uint32_t*)&l23);
}

// ---------------------------------------------------------------------------
// Kernel 2b: P (128,4096) -> Pt (4096,128) bf16 hi/lo. grid (128,4,NB), blk (32,8)
// ---------------------------------------------------------------------------
__global__ __launch_bounds__(256) void trP_kernel()
{
    int b = blockIdx.z;
    const float* P = g_P + (size_t)b * CB * NSP;
    __shared__ float sm[32][33];
    int tx = threadIdx.x, ty = threadIdx.y;
    int n0 = blockIdx.x << 5, k0 = blockIdx.y << 5;
#pragma unroll
    for (int i = 0; i < 4; i++)
        sm[ty + i * 8][tx] = P[(size_t)(k0 + ty + i * 8) * NSP + n0 + tx];
    __syncthreads();
#pragma unroll
    for (int i = 0; i < 4; i++) {
        int n = n0 + ty + i * 8, k = k0 + tx;
        float v = sm[tx][ty + i * 8];
        __nv_bfloat16 h = __float2bfloat16_rn(v);
        g_Phi[((size_t)b * NSP + n) * CB + k] = h;
        g_Plo[((size_t)b * NSP + n) * CB + k] = __float2bfloat16_rn(v - __bfloat162float(h));
    }
}

// ---------------------------------------------------------------------------
// Kernel 3: persistent column-strip scores. grid (32, NB), 512 thr.
// CTA owns 128 columns (B strip resident); loops 32 row tiles with cp.async
// double-buffered A. Computes full Z per column in-register -> writes g_Zr.
// ---------------------------------------------------------------------------
__global__ __launch_bounds__(512, 1) void scores_mma_kernel()
{
    extern __shared__ __align__(16) char smem[];
    const int tid = threadIdx.x;
    const int wid = tid >> 5, lane = tid & 31;
    const int b = blockIdx.y;
    const int colBase = blockIdx.x << 7;

    const uint32_t sb = smem_to_u32(smem);
    const __nv_bfloat16* Ah = g_Thi + (size_t)b * NSP * CB;
    const __nv_bfloat16* Al = g_Tlo + (size_t)b * NSP * CB;
    const __nv_bfloat16* Bh = g_Phi + ((size_t)b * NSP + colBase) * CB;
    const __nv_bfloat16* Bl = g_Plo + ((size_t)b * NSP + colBase) * CB;

    // ---- one-time B staging + A(0), then A(1) (cp.async groups) ----
    // granule id: r = gid>>4 (row 0..127), g16 = gid&15 (16B granule in row)
    {
#pragma unroll
        for (int i = 0; i < 4; i++) {
            int gid = tid + i * 512;
            int r = gid >> 4, g16 = gid & 15;
            size_t gi = (size_t)r * CB + g16 * 8;
            uint32_t so = r * 272 + g16 * 16;
            CP_ASYNC16(sb + SP_BHI + so, Bh + gi);
            CP_ASYNC16(sb + SP_BLO + so, Bl + gi);
            CP_ASYNC16(sb + SP_A0 + so,          Ah + gi);   // A tile rt=0 rows 0..127
            CP_ASYNC16(sb + SP_A0 + SP_ATL + so, Al + gi);
        }
        CP_COMMIT();
#pragma unroll
        for (int i = 0; i < 4; i++) {
            int gid = tid + i * 512;
            int r = gid >> 4, g16 = gid & 15;
            size_t gi = (size_t)(128 + r) * CB + g16 * 8;    // A tile rt=1
            uint32_t so = r * 272 + g16 * 16;
            CP_ASYNC16(sb + SP_A0 + SP_ABUF + so,          Ah + gi);
            CP_ASYNC16(sb + SP_A0 + SP_ABUF + SP_ATL + so, Al + gi);
        }
        CP_COMMIT();
    }

    const int mrow = (wid & 3) * 32, ncol = (wid >> 2) * 32;
    const int aR = lane & 15, aK = (lane >> 4) * 8;
    const int bN = (lane & 7) + ((lane >> 4) << 3), bK = ((lane >> 3) & 1) * 8;
    const int g = lane >> 2, tig = lane & 3;

    __nv_bfloat16* Shi = g_Shi + (size_t)b * NSP * NSP;
    __nv_bfloat16* Slo = g_Slo + (size_t)b * NSP * NSP;

    float csum[8];
#pragma unroll
    for (int c = 0; c < 8; c++) csum[c] = 0.f;

    for (int rt = 0; rt < 32; rt++) {
        // prefetch A(rt+1)
        if (rt < 31) {
            uint32_t bufn = sb + SP_A0 + ((rt + 1) & 1) * SP_ABUF;
            const __nv_bfloat16* Anh = Ah + (size_t)(rt + 1) * 128 * CB;
            const __nv_bfloat16* Anl = Al + (size_t)(rt + 1) * 128 * CB;
#pragma unroll
            for (int i = 0; i < 4; i++) {
                int gid = tid + i * 512;
                int r = gid >> 4, g16 = gid & 15;
                size_t gi = (size_t)r * CB + g16 * 8;
                uint32_t so = r * 272 + g16 * 16;
                CP_ASYNC16(bufn + so,          Anh + gi);
                CP_ASYNC16(bufn + SP_ATL + so, Anl + gi);
            }
            CP_COMMIT();
            CP_WAIT1();
        } else {
            CP_WAIT0();
        }
        __syncthreads();

        uint32_t bufA = sb + SP_A0 + (rt & 1) * SP_ABUF;

        float acc[2][4][4];
#pragma unroll
        for (int mi = 0; mi < 2; mi++)
#pragma unroll
            for (int n = 0; n < 4; n++)
#pragma unroll
                for (int q = 0; q < 4; q++) acc[mi][n][q] = 0.f;

#pragma unroll
        for (int ks = 0; ks < 8; ks++) {
            int k0 = ks * 16;
            uint32_t ahi[2][4], alo[2][4], bhi[2][4], blo[2][4];
#pragma unroll
            for (int mi = 0; mi < 2; mi++) {
                uint32_t ad = bufA + (mrow + mi * 16 + aR) * 272 + (k0 + aK) * 2;
                ldsm4(ahi[mi], ad);
                ldsm4(alo[mi], ad + SP_ATL);
            }
#pragma unroll
            for (int nj = 0; nj < 2; nj++) {
                uint32_t bd = sb + SP_BHI + (ncol + nj * 16 + bN) * 272 + (k0 + bK) * 2;
                ldsm4(bhi[nj], bd);
                ldsm4(blo[nj], bd + (SP_BLO - SP_BHI));
            }
#pragma unroll
            for (int mi = 0; mi < 2; mi++)
#pragma unroll
                for (int nj = 0; nj < 2; nj++) {
                    mma16816(acc[mi][nj * 2],     ahi[mi], bhi[nj][0], bhi[nj][1]);
                    mma16816(acc[mi][nj * 2 + 1], ahi[mi], bhi[nj][2], bhi[nj][3]);
                }
#pragma unroll
            for (int mi = 0; mi < 2; mi++)
#pragma unroll
                for (int nj = 0; nj < 2; nj++) {
                    mma16816(acc[mi][nj * 2],     ahi[mi], blo[nj][0], blo[nj][1]);
                    mma16816(acc[mi][nj * 2 + 1], ahi[mi], blo[nj][2], blo[nj][3]);
                }
#pragma unroll
            for (int mi = 0; mi < 2; mi++)
#pragma unroll
                for (int nj = 0; nj < 2; nj++) {
                    mma16816(acc[mi][nj * 2],     alo[mi], bhi[nj][0], bhi[nj][1]);
                    mma16816(acc[mi][nj * 2 + 1], alo[mi], bhi[nj][2], bhi[nj][3]);
                }
        }

        // epilogue: exp, write Shi/Slo, accumulate column partials
#pragma unroll
        for (int mi = 0; mi < 2; mi++)
#pragma unroll
            for (int rr = 0; rr < 2; rr++) {
                int row = rt * 128 + mrow + mi * 16 + g + rr * 8;
                size_t rbase = (size_t)row * NSP + colBase;
#pragma unroll
                for (int ni = 0; ni < 4; ni++) {
                    int coll = ncol + ni * 8 + tig * 2;
                    float e0 = __expf(acc[mi][ni][rr * 2 + 0]);
                    float e1 = __expf(acc[mi][ni][rr * 2 + 1]);
                    __nv_bfloat16 h0 = __float2bfloat16_rn(e0);
                    __nv_bfloat16 h1 = __float2bfloat16_rn(e1);
                    __nv_bfloat162 hp(h0, h1);
                    __nv_bfloat162 lp(__float2bfloat16_rn(e0 - __bfloat162float(h0)),
                                      __float2bfloat16_rn(e1 - __bfloat162float(h1)));
                    *(uint32_t*)(Shi + rbase + coll) = *(uint32_t*)&hp;
                    *(uint32_t*)(Slo + rbase + coll) = *(uint32_t*)&lp;
                    csum[ni * 2 + 0] += e0;
                    csum[ni * 2 + 1] += e1;
                }
            }
        __syncthreads();
    }

    // ---- final Z reduction (deterministic) ----
    // reduce over g lanes (rows within warp)
#pragma unroll
    for (int c = 0; c < 8; c++) {
        csum[c] += __shfl_xor_sync(0xffffffffu, csum[c], 4);
        csum[c] += __shfl_xor_sync(0xffffffffu, csum[c], 8);
        csum[c] += __shfl_xor_sync(0xffffffffu, csum[c], 16);
    }
    // A buffers are free now; use as float redZ[4][128]
    float (*redZ)[128] = (float(*)[128])(smem + SP_A0);
    int wr = wid & 3;                  // row-warp group
    if (lane < 4) {
#pragma unroll
        for (int ni = 0; ni < 4; ni++) {
            int col = ncol + ni * 8 + lane * 2;
            redZ[wr][col]     = csum[ni * 2 + 0];
            redZ[wr][col + 1] = csum[ni * 2 + 1];
        }
    }
    __syncthreads();
    if (tid < 128) {
        float z = redZ[0][tid] + redZ[1][tid] + redZ[2][tid] + redZ[3][tid];
        g_Zr[b * NSP + colBase + tid] = 1.0f / z;
    }
}

// ---------------------------------------------------------------------------
// Kernel 5: Gt'(c,m) = Gview[m][c] * Zr[m], bf16 hi/lo. grid (128,4,NB), blk (32,8)
// ---------------------------------------------------------------------------
__global__ __launch_bounds__(256) void gscale_kernel()
{
    int b = blockIdx.z;
    const float* Gf = g_G + (size_t)b * CB * NSP;
    const float* Zr = g_Zr + b * NSP;
    __shared__ float sm[32][33];
    int tx = threadIdx.x, ty = threadIdx.y;
    int m0 = blockIdx.x << 5, c0 = blockIdx.y << 5;
#pragma unroll
    for (int i = 0; i < 4; i++) {
        int m = m0 + ty + i * 8;
        sm[ty + i * 8][tx] = Gf[(size_t)m * CB + c0 + tx] * Zr[m];
    }
    __syncthreads();
#pragma unroll
    for (int i = 0; i < 4; i++) {
        int c = c0 + ty + i * 8, m = m0 + tx;
        float v = sm[tx][ty + i * 8];
        __nv_bfloat16 h = __float2bfloat16_rn(v);
        g_Ghi[((size_t)b * CB + c) * NSP + m] = h;
        g_Glo[((size_t)b * CB + c) * NSP + m] = __float2bfloat16_rn(v - __bfloat162float(h));
    }
}

// ---------------------------------------------------------------------------
// Kernel 6: Y(128x128) = expS @ (Gt')^T. 512 thr, 16 warps (32x32 warp tiles),
// K=4096 in 64-wide chunks, cp.async TRIPLE-buffered. grid (32, NB) = 128 CTAs.
// ---------------------------------------------------------------------------
__global__ __launch_bounds__(512, 1) void y_mma_kernel()
{
    extern __shared__ __align__(16) char smem[];
    const int tid = threadIdx.x;
    const int wid = tid >> 5, lane = tid & 31;
    const int b = blockIdx.y;
    const int rowBase = blockIdx.x << 7;

    const uint32_t sb = smem_to_u32(smem);
    const int mrow = (wid & 3) * 32, ncol = (wid >> 2) * 32;
    const int aR = lane & 15, aK = (lane >> 4) * 8;
    const int bN = (lane & 7) + ((lane >> 4) << 3), bK = ((lane >> 3) & 1) * 8;

    const __nv_bfloat16* Sh = g_Shi + (size_t)b * NSP * NSP;
    const __nv_bfloat16* Sl = g_Slo + (size_t)b * NSP * NSP;
    const __nv_bfloat16* Gh = g_Ghi + (size_t)b * CB * NSP;
    const __nv_bfloat16* Gl = g_Glo + (size_t)b * CB * NSP;

    const int arow = tid >> 3, ag = tid & 7;     // A: rows arow, arow+64; 8 granules/row
    const int brow = tid >> 2, bg = tid & 3;     // B: 128 rows, granules bg and bg+4

    float acc[2][4][4];
#pragma unroll
    for (int mi = 0; mi < 2; mi++)
#pragma unroll
        for (int n = 0; n < 4; n++)
#pragma unroll
            for (int q = 0; q < 4; q++) acc[mi][n][q] = 0.f;

#define Y_STAGE(kt, s) do { \
    int kg = (kt) << 6; \
    uint32_t bufs = sb + (s) * YB_BUF; \
    _Pragma("unroll") \
    for (int i = 0; i < 2; i++) { \
        int r = arow + i * 64; \
        uint32_t so = bufs + r * 144 + ag * 16; \
        CP_ASYNC16(so,            Sh + (size_t)(rowBase + r) * NSP + kg + ag * 8); \
        CP_ASYNC16(so + YB_TILE,  Sl + (size_t)(rowBase + r) * NSP + kg + ag * 8); \
    } \
    { \
        uint32_t so = bufs + 2 * YB_TILE + brow * 144 + bg * 16; \
        const __nv_bfloat16* gh = Gh + (size_t)brow * NSP + kg + bg * 8; \
        const __nv_bfloat16* gl = Gl + (size_t)brow * NSP + kg + bg * 8; \
        CP_ASYNC16(so,                 gh); \
        CP_ASYNC16(so + YB_TILE,       gl); \
        CP_ASYNC16(so + 64,            gh + 32); \
        CP_ASYNC16(so + YB_TILE + 64,  gl + 32); \
    } \
    CP_COMMIT(); \
} while (0)

    Y_STAGE(0, 0);
    Y_STAGE(1, 1);

    for (int kt = 0; kt < 64; kt++) {
        if (kt + 2 < 64) Y_STAGE(kt + 2, (kt + 2) % 3);
        if (kt < 62)      { CP_WAIT2(); }
        else if (kt == 62){ CP_WAIT1(); }
        else              { CP_WAIT0(); }
        __syncthreads();

        uint32_t bufs = sb + (kt % 3) * YB_BUF;
#pragma unroll
        for (int ks = 0; ks < 4; ks++) {
            int k0 = ks * 16;
            uint32_t ahi[2][4], alo[2][4], bhi[2][4], blo[2][4];
#pragma unroll
            for (int mi = 0; mi < 2; mi++) {
                uint32_t ad = bufs + (mrow + mi * 16 + aR) * 144 + (k0 + aK) * 2;
                ldsm4(ahi[mi], ad);
                ldsm4(alo[mi], ad + YB_TILE);
            }
#pragma unroll
            for (int nj = 0; nj < 2; nj++) {
                uint32_t bd = bufs + 2 * YB_TILE + (ncol + nj * 16 + bN) * 144 + (k0 + bK) * 2;
                ldsm4(bhi[nj], bd);
                ldsm4(blo[nj], bd + YB_TILE);
            }
#pragma unroll
            for (int mi = 0; mi < 2; mi++)
#pragma unroll
                for (int nj = 0; nj < 2; nj++) {
                    mma16816(acc[mi][nj * 2],     ahi[mi], bhi[nj][0], bhi[nj][1]);
                    mma16816(acc[mi][nj * 2 + 1], ahi[mi], bhi[nj][2], bhi[nj][3]);
                }
#pragma unroll
            for (int mi = 0; mi < 2; mi++)
#pragma unroll
                for (int nj = 0; nj < 2; nj++) {
                    mma16816(acc[mi][nj * 2],     ahi[mi], blo[nj][0], blo[nj][1]);
                    mma16816(acc[mi][nj * 2 + 1], ahi[mi], blo[nj][2], blo[nj][3]);
                }
#pragma unroll
            for (int mi = 0; mi < 2; mi++)
#pragma unroll
                for (int nj = 0; nj < 2; nj++) {
                    mma16816(acc[mi][nj * 2],     alo[mi], bhi[nj][0], bhi[nj][1]);
                    mma16816(acc[mi][nj * 2 + 1], alo[mi], bhi[nj][2], bhi[nj][3]);
                }
        }
        __syncthreads();
    }

    const int g = lane >> 2, tig = lane & 3;
#pragma unroll
    for (int mi = 0; mi < 2; mi++)
#pragma unroll
        for (int rr = 0; rr < 2; rr++) {
            int row = rowBase + mrow + mi * 16 + g + rr * 8;
            float* yrow = g_Y + ((size_t)b * NSP + row) * CB;
#pragma unroll
            for (int ni = 0; ni < 4; ni++) {
                int col = ncol + ni * 8 + tig * 2;
                *(float2*)(yrow + col) =
                    make_float2(acc[mi][ni][rr * 2], acc[mi][ni][rr * 2 + 1]);
            }
        }
#undef Y_STAGE
}

// ---------------------------------------------------------------------------
// Kernel 7: Out = W_w @ Yview + W_b + x (SIMT FFMA2). grid (32,2,NB)
// ---------------------------------------------------------------------------
__global__ __launch_bounds__(256, 2) void out_kernel(
    const float* __restrict__ x,
    const float* __restrict__ Ww, const float* __restrict__ Wb,
    float* __restrict__ out)
{
    int b = blockIdx.z;
    const float* Byc = g_Y + (size_t)b * CB * NSP;
    const float* xb  = x + (size_t)b * CIN * NSP;
    float* Cb_ = out + (size_t)b * CIN * NSP;

    __shared__ __align__(16) float As[8][132];
    __shared__ __align__(16) float Bs[8][128];
    int tid  = threadIdx.x;
    int aRow = tid >> 1, aCol = (tid & 1) << 2;
    int bRow = tid >> 5, bCol = (tid & 31) << 2;
    int ty = tid >> 4, tx = tid & 15;
    int rowBase = blockIdx.y << 7;
    int colBase = blockIdx.x << 7;

    u64 acc[8][4];
#pragma unroll
    for (int i = 0; i < 8; i++)
#pragma unroll
        for (int jp = 0; jp < 4; jp++) acc[i][jp] = pk2(0.f, 0.f);

    for (int k0 = 0; k0 < CB; k0 += 8) {
        float4 av = *(const float4*)(Ww + (size_t)(rowBase + aRow) * CB + k0 + aCol);
        As[aCol + 0][aRow] = av.x;
        As[aCol + 1][aRow] = av.y;
        As[aCol + 2][aRow] = av.z;
        As[aCol + 3][aRow] = av.w;
        *(float4*)&Bs[bRow][bCol] =
            *(const float4*)(Byc + (size_t)(k0 + bRow) * NSP + colBase + bCol);
        __syncthreads();
#pragma unroll
        for (int k = 0; k < 8; k++) {
            float ra[8];
            *(float4*)(ra)     = *(const float4*)&As[k][ty << 2];
            *(float4*)(ra + 4) = *(const float4*)&As[k][64 + (ty << 2)];
            const u64* bp0 = (const u64*)&Bs[k][tx << 2];
            const u64* bp1 = (const u64*)&Bs[k][64 + (tx << 2)];
            u64 rb[4] = {bp0[0], bp0[1], bp1[0], bp1[1]};
#pragma unroll
            for (int i = 0; i < 8; i++) {
                u64 aa = pk2(ra[i], ra[i]);
#pragma unroll
                for (int jp = 0; jp < 4; jp++)
                    acc[i][jp] = fma2(aa, rb[jp], acc[i][jp]);
            }
        }
        __syncthreads();
    }
#pragma unroll
    for (int i = 0; i < 8; i++) {
        int row = rowBase + ((i >> 2) << 6) + (ty << 2) + (i & 3);
        float bv = Wb[row];
#pragma unroll
        for (int jh = 0; jh < 2; jh++) {
            int col = colBase + (jh << 6) + (tx << 2);
            float4 xv = *(const float4*)(xb + (size_t)row * NSP + col);
            float4 v;
            upk2(acc[i][2 * jh],     v.x, v.y);
            upk2(acc[i][2 * jh + 1], v.z, v.w);
            v.x += bv + xv.x; v.y += bv + xv.y;
            v.z += bv + xv.z; v.w += bv + xv.w;
            *(float4*)(Cb_ + (size_t)row * NSP + col) = v;
        }
    }
}

// ---------------------------------------------------------------------------
extern "C" void kernel_launch(void* const* d_in, const int* in_sizes, int n_in,
                              void* d_out, int out_size)
{
    const float* x  = (const float*)d_in[0];
    const float* tw = (const float*)d_in[1];
    const float* tb = (const float*)d_in[2];
    const float* pw = (const float*)d_in[3];
    const float* pb = (const float*)d_in[4];
    const float* gw = (const float*)d_in[5];
    const float* gb = (const float*)d_in[6];
    const float* Ww = (const float*)d_in[7];
    const float* Wb = (const float*)d_in[8];
    float* out = (float*)d_out;

    cudaFuncSetAttribute(scores_mma_kernel, cudaFuncAttributeMaxDynamicSharedMemorySize, SC_BYTES);
    cudaFuncSetAttribute(y_mma_kernel, cudaFuncAttributeMaxDynamicSharedMemorySize, Y_BYTES);

    conv_tpg_kernel<<<dim3(32, 1, 12), 256>>>(x, tw, tb, pw, pb, gw, gb);
    cvtT_kernel<<<2048, 256>>>();
    trP_kernel<<<dim3(128, 4, NB), dim3(32, 8)>>>();
    scores_mma_kernel<<<dim3(32, NB), 512, SC_BYTES>>>();
    gscale_kernel<<<dim3(128, 4, NB), dim3(32, 8)>>>();
    y_mma_kernel<<<dim3(32, NB), 512, Y_BYTES>>>();
    out_kernel<<<dim3(32, 2, NB), 256>>>(x, Ww, Wb, out);
}